// round 5
// baseline (speedup 1.0000x reference)
#include <cuda_runtime.h>
#include <math.h>
#include <float.h>

// Problem constants
#define BB   2
#define DD   512
#define NN   2048
#define HH   8
#define DKK  64
#define DD2  1024
#define EPSV 1e-5f

// ---------------------------------------------------------------------------
// Scratch (static __device__ arrays; no allocation allowed)
// ---------------------------------------------------------------------------
__device__ float g_q [BB * DD  * NN];  // q projection, layout (B, D, N), d = dk*H + h
__device__ float g_k [BB * DD  * NN];
__device__ float g_v [BB * DD  * NN];
__device__ float g_x [BB * DD  * NN];  // attention output (merged heads), (B, D, N)
__device__ float g_xm[BB * DD  * NN];  // after Wm conv
__device__ float g_h [BB * DD2 * NN];  // after W1 + BN + ReLU, (B, 2D, N)

// ---------------------------------------------------------------------------
// Generic fp32 GEMM body: out[b] (O x N) = W (O x I) @ X[b] (I x N) + bias
// Tiles: 128x128x16, 256 threads, 8x8 micro-tile.
// MODE 0: plain + bias
// MODE 1: X rows [0,512) from X, rows [512,1024) from X2 (concat), then
//         BatchNorm (running stats) + ReLU epilogue.
// ---------------------------------------------------------------------------
template <int MODE>
__device__ __forceinline__ void gemm_body(
    const float* __restrict__ W,
    const float* __restrict__ X,      // batch base
    const float* __restrict__ X2,     // batch base (MODE 1 only)
    const float* __restrict__ bias,
    const float* __restrict__ rmean, const float* __restrict__ rvar,
    const float* __restrict__ gam,   const float* __restrict__ bet,
    float* __restrict__ out,          // batch base
    int O, int I)
{
    __shared__ float As[16][132];  // [k][o]  (W tile, transposed)
    __shared__ float Bs[16][132];  // [k][n]  (X tile)

    const int tid = threadIdx.x;           // 256
    const int ty  = tid >> 4;              // 0..15
    const int tx  = tid & 15;              // 0..15
    const int n0  = blockIdx.x * 128;
    const int o0  = blockIdx.y * 128;

    float acc[8][8];
#pragma unroll
    for (int i = 0; i < 8; ++i)
#pragma unroll
        for (int j = 0; j < 8; ++j) acc[i][j] = 0.f;

    const int wr = tid >> 2;               // 0..63  (W tile row)
    const int wc = (tid & 3) << 2;         // 0,4,8,12
    const int xr = tid >> 4;               // 0..15  (X tile row)
    const int xj = (tid & 15) << 2;        // 0..60

    for (int k0 = 0; k0 < I; k0 += 16) {
        // --- load W tile (transposed into As) ---
#pragma unroll
        for (int s = 0; s < 2; ++s) {
            const float4 w4 = *(const float4*)(W + (size_t)(o0 + wr + s * 64) * I + k0 + wc);
            As[wc + 0][wr + s * 64] = w4.x;
            As[wc + 1][wr + s * 64] = w4.y;
            As[wc + 2][wr + s * 64] = w4.z;
            As[wc + 3][wr + s * 64] = w4.w;
        }
        // --- load X tile ---
        {
            const int irow = k0 + xr;
            const float* src;
            if (MODE == 1)
                src = (irow < DD) ? (X + (size_t)irow * NN) : (X2 + (size_t)(irow - DD) * NN);
            else
                src = X + (size_t)irow * NN;
#pragma unroll
            for (int s = 0; s < 2; ++s)
                *(float4*)&Bs[xr][xj + s * 64] = *(const float4*)(src + n0 + xj + s * 64);
        }
        __syncthreads();

#pragma unroll
        for (int kk = 0; kk < 16; ++kk) {
            float ar[8], br[8];
            *(float4*)&ar[0] = *(const float4*)&As[kk][ty * 8];
            *(float4*)&ar[4] = *(const float4*)&As[kk][ty * 8 + 4];
            *(float4*)&br[0] = *(const float4*)&Bs[kk][tx * 8];
            *(float4*)&br[4] = *(const float4*)&Bs[kk][tx * 8 + 4];
#pragma unroll
            for (int i = 0; i < 8; ++i)
#pragma unroll
                for (int j = 0; j < 8; ++j)
                    acc[i][j] += ar[i] * br[j];
        }
        __syncthreads();
    }

    // --- epilogue ---
#pragma unroll
    for (int i = 0; i < 8; ++i) {
        const int o = o0 + ty * 8 + i;
        const float badd = bias[o];
        float sc = 1.f, sh = badd;
        if (MODE == 1) {
            const float s = gam[o] * rsqrtf(rvar[o] + EPSV);
            sc = s;
            sh = (badd - rmean[o]) * s + bet[o];
        }
        float vals[8];
#pragma unroll
        for (int j = 0; j < 8; ++j) {
            float v;
            if (MODE == 1) {
                v = acc[i][j] * sc + sh;
                v = fmaxf(v, 0.f);
            } else {
                v = acc[i][j] + badd;
            }
            vals[j] = v;
        }
        float* op = out + (size_t)o * NN + n0 + tx * 8;
        *(float4*)op       = *(float4*)&vals[0];
        *(float4*)(op + 4) = *(float4*)&vals[4];
    }
}

// ---------------------------------------------------------------------------
// Fused q/k/v projection: one launch, grid.z = 3 * B selects (proj, batch)
// ---------------------------------------------------------------------------
__global__ __launch_bounds__(256, 2)
void qkv_kernel(const float* __restrict__ xq, const float* __restrict__ xk,
                const float* __restrict__ xv,
                const float* __restrict__ Wq, const float* __restrict__ bq,
                const float* __restrict__ Wk, const float* __restrict__ bk,
                const float* __restrict__ Wv, const float* __restrict__ bv)
{
    const int z   = blockIdx.z;   // 0..5
    const int b   = z & 1;        // BB == 2
    const int sel = z >> 1;
    const float *W, *X, *bi;
    float* out;
    if (sel == 0)      { W = Wq; X = xq; bi = bq; out = g_q; }
    else if (sel == 1) { W = Wk; X = xk; bi = bk; out = g_k; }
    else               { W = Wv; X = xv; bi = bv; out = g_v; }
    gemm_body<0>(W, X + (size_t)b * DD * NN, nullptr, bi,
                 nullptr, nullptr, nullptr, nullptr,
                 out + (size_t)b * DD * NN, DD, DD);
}

template <int MODE>
__global__ __launch_bounds__(256, 2)
void gemm_kernel(const float* __restrict__ W, const float* __restrict__ X,
                 const float* __restrict__ X2, const float* __restrict__ bias,
                 const float* __restrict__ rmean, const float* __restrict__ rvar,
                 const float* __restrict__ gam,   const float* __restrict__ bet,
                 float* __restrict__ out, int O, int I)
{
    const int b = blockIdx.z;
    const size_t xs = (MODE == 1) ? (size_t)DD * NN : (size_t)I * NN;
    gemm_body<MODE>(W, X + (size_t)b * xs,
                    (MODE == 1) ? (X2 + (size_t)b * DD * NN) : nullptr,
                    bias, rmean, rvar, gam, bet,
                    out + (size_t)b * O * NN, O, I);
}

// ---------------------------------------------------------------------------
// Flash attention: per-CTA 64 query rows x one (b, h); streams 64-wide key
// tiles with online softmax. 128 threads, 8x4 micro-tile.
// q/k/v layout: (B, D, N) with channel d = dk*H + h.
// ---------------------------------------------------------------------------
#define LDP 68
#define ATTN_SMEM (4 * 64 * LDP * 4)

__global__ __launch_bounds__(128, 3)
void attn_kernel(const int* __restrict__ mask)
{
    extern __shared__ float smp[];
    float* Qs = smp;                 // [dk][r]  64 x 68
    float* Ks = smp + 1 * 64 * LDP;  // [dk][c]
    float* Vs = smp + 2 * 64 * LDP;  // [c][dk]
    float* Ss = smp + 3 * 64 * LDP;  // [c][r], reused as [dk][r] for output
    __shared__ float m_row[64], l_row[64], alpha_s[64], mnew_s[64];
    __shared__ float pred[64][2];

    const int tid = threadIdx.x;     // 128
    const int b   = blockIdx.z;
    const int h   = blockIdx.y;
    const int n0  = blockIdx.x * 64;
    const int ty  = tid >> 4;        // 0..7  -> rows ty*8..+7
    const int tx  = tid & 15;        // 0..15 -> cols tx*4..+3
    const int dkl = tid >> 1;        // 0..63 (loader: dk row)
    const int c0l = (tid & 1) << 5;  // 0 or 32

    const size_t rowbase = ((size_t)b * DD + (size_t)dkl * HH + h) * NN;

    // Load Q tile (transposed: Qs[dk][r])
    {
        const float* qrow = g_q + rowbase + n0 + c0l;
#pragma unroll
        for (int s = 0; s < 8; ++s)
            *(float4*)&Qs[dkl * LDP + c0l + s * 4] = *(const float4*)(qrow + s * 4);
    }
    if (tid < 64) { m_row[tid] = -INFINITY; l_row[tid] = 0.f; }

    float oacc[8][4];
#pragma unroll
    for (int i = 0; i < 8; ++i)
#pragma unroll
        for (int j = 0; j < 4; ++j) oacc[i][j] = 0.f;

    const float* kb = g_k + rowbase;
    const float* vb = g_v + rowbase;
    const int*   mb = mask + (size_t)b * NN * NN;

    for (int m0 = 0; m0 < NN; m0 += 64) {
        __syncthreads();  // protect Ks/Vs/Ss reuse from previous iteration
        // Load K tile (Ks[dk][c]) and V tile (transposed: Vs[c][dk])
#pragma unroll
        for (int s = 0; s < 8; ++s)
            *(float4*)&Ks[dkl * LDP + c0l + s * 4] = *(const float4*)(kb + m0 + c0l + s * 4);
#pragma unroll
        for (int s = 0; s < 8; ++s) {
            const float4 vv = *(const float4*)(vb + m0 + c0l + s * 4);
            Vs[(c0l + s * 4 + 0) * LDP + dkl] = vv.x;
            Vs[(c0l + s * 4 + 1) * LDP + dkl] = vv.y;
            Vs[(c0l + s * 4 + 2) * LDP + dkl] = vv.z;
            Vs[(c0l + s * 4 + 3) * LDP + dkl] = vv.w;
        }
        __syncthreads();

        // S = Q^T K  (8 rows x 4 cols per thread)
        float sv[8][4];
#pragma unroll
        for (int i = 0; i < 8; ++i)
#pragma unroll
            for (int j = 0; j < 4; ++j) sv[i][j] = 0.f;
#pragma unroll
        for (int kk = 0; kk < 64; ++kk) {
            float ar[8], br[4];
            *(float4*)&ar[0] = *(const float4*)&Qs[kk * LDP + ty * 8];
            *(float4*)&ar[4] = *(const float4*)&Qs[kk * LDP + ty * 8 + 4];
            *(float4*)&br[0] = *(const float4*)&Ks[kk * LDP + tx * 4];
#pragma unroll
            for (int i = 0; i < 8; ++i)
#pragma unroll
                for (int j = 0; j < 4; ++j)
                    sv[i][j] += ar[i] * br[j];
        }
        // scale + mask, store transposed into Ss[c][r]
#pragma unroll
        for (int i = 0; i < 8; ++i) {
            const int r = ty * 8 + i;
            const int4 mk = *(const int4*)(mb + (size_t)(n0 + r) * NN + m0 + tx * 4);
            Ss[(tx * 4 + 0) * LDP + r] = (mk.x == 0) ? -1e9f : sv[i][0] * 0.125f;
            Ss[(tx * 4 + 1) * LDP + r] = (mk.y == 0) ? -1e9f : sv[i][1] * 0.125f;
            Ss[(tx * 4 + 2) * LDP + r] = (mk.z == 0) ? -1e9f : sv[i][2] * 0.125f;
            Ss[(tx * 4 + 3) * LDP + r] = (mk.w == 0) ? -1e9f : sv[i][3] * 0.125f;
        }
        __syncthreads();

        // --- online softmax: 2 threads per row ---
        {
            const int r = tid >> 1, sg = tid & 1;
            float mx = -INFINITY;
#pragma unroll
            for (int c = 0; c < 32; ++c)
                mx = fmaxf(mx, Ss[(sg * 32 + c) * LDP + r]);
            pred[r][sg] = mx;
        }
        __syncthreads();
        if (tid < 64) {
            const float mloc = fmaxf(pred[tid][0], pred[tid][1]);
            const float mold = m_row[tid];
            const float mn   = fmaxf(mold, mloc);
            mnew_s[tid]  = mn;
            alpha_s[tid] = __expf(mold - mn);  // exp(-inf) = 0 on first tile
        }
        __syncthreads();
        {
            const int r = tid >> 1, sg = tid & 1;
            const float mn = mnew_s[r];
            float sum = 0.f;
#pragma unroll
            for (int c = 0; c < 32; ++c) {
                const float e = __expf(Ss[(sg * 32 + c) * LDP + r] - mn);
                Ss[(sg * 32 + c) * LDP + r] = e;
                sum += e;
            }
            pred[r][sg] = sum;
        }
        __syncthreads();
        if (tid < 64) {
            m_row[tid] = mnew_s[tid];
            l_row[tid] = l_row[tid] * alpha_s[tid] + pred[tid][0] + pred[tid][1];
        }
        __syncthreads();

        // rescale running O, then O += P @ V
#pragma unroll
        for (int i = 0; i < 8; ++i) {
            const float al = alpha_s[ty * 8 + i];
#pragma unroll
            for (int j = 0; j < 4; ++j) oacc[i][j] *= al;
        }
#pragma unroll
        for (int kk = 0; kk < 64; ++kk) {
            float ar[8], br[4];
            *(float4*)&ar[0] = *(const float4*)&Ss[kk * LDP + ty * 8];
            *(float4*)&ar[4] = *(const float4*)&Ss[kk * LDP + ty * 8 + 4];
            *(float4*)&br[0] = *(const float4*)&Vs[kk * LDP + tx * 4];
#pragma unroll
            for (int i = 0; i < 8; ++i)
#pragma unroll
                for (int j = 0; j < 4; ++j)
                    oacc[i][j] += ar[i] * br[j];
        }
    }
    __syncthreads();

    // normalize, stage transposed (Ss[dk][r]), write coalesced to (B,D,N)
#pragma unroll
    for (int i = 0; i < 8; ++i) {
        const int r = ty * 8 + i;
        const float inv = 1.f / l_row[r];
#pragma unroll
        for (int j = 0; j < 4; ++j)
            Ss[(tx * 4 + j) * LDP + r] = oacc[i][j] * inv;
    }
    __syncthreads();
    {
        float* xr = g_x + rowbase + n0 + c0l;
#pragma unroll
        for (int s = 0; s < 8; ++s)
            *(float4*)(xr + s * 4) = *(const float4*)&Ss[dkl * LDP + c0l + s * 4];
    }
}

// ---------------------------------------------------------------------------
// Launch
// ---------------------------------------------------------------------------
extern "C" void kernel_launch(void* const* d_in, const int* in_sizes, int n_in,
                              void* d_out, int out_size)
{
    const float* init_query = (const float*)d_in[0];
    const float* key_t      = (const float*)d_in[1];
    const float* value      = (const float*)d_in[2];
    const int*   mask       = (const int*)  d_in[3];
    const float* Wq    = (const float*)d_in[4];
    const float* bq    = (const float*)d_in[5];
    const float* Wk    = (const float*)d_in[6];
    const float* bk    = (const float*)d_in[7];
    const float* Wv    = (const float*)d_in[8];
    const float* bv    = (const float*)d_in[9];
    const float* Wm    = (const float*)d_in[10];
    const float* bm    = (const float*)d_in[11];
    const float* W1    = (const float*)d_in[12];
    const float* b1    = (const float*)d_in[13];
    const float* gamma = (const float*)d_in[14];
    const float* beta  = (const float*)d_in[15];
    const float* rmean = (const float*)d_in[16];
    const float* rvar  = (const float*)d_in[17];
    const float* W2    = (const float*)d_in[18];
    const float* b2    = (const float*)d_in[19];
    float* out = (float*)d_out;

    float *p_x, *p_xm, *p_h;
    cudaGetSymbolAddress((void**)&p_x,  g_x);
    cudaGetSymbolAddress((void**)&p_xm, g_xm);
    cudaGetSymbolAddress((void**)&p_h,  g_h);

    cudaFuncSetAttribute(attn_kernel, cudaFuncAttributeMaxDynamicSharedMemorySize, ATTN_SMEM);

    // 1) q/k/v projections (one fused launch)
    qkv_kernel<<<dim3(16, 4, 6), 256>>>(init_query, key_t, value,
                                        Wq, bq, Wk, bk, Wv, bv);
    // 2) flash attention -> g_x (B, D, N)
    attn_kernel<<<dim3(NN / 64, HH, BB), 128, ATTN_SMEM>>>(mask);
    // 3) merge conv: g_xm = Wm @ g_x + bm
    gemm_kernel<0><<<dim3(16, 4, BB), 256>>>(Wm, p_x, nullptr, bm,
                                             nullptr, nullptr, nullptr, nullptr,
                                             p_xm, DD, DD);
    // 4) W1 @ [xm ; init_query] + b1, BN (running stats) + ReLU -> g_h
    gemm_kernel<1><<<dim3(16, 8, BB), 256>>>(W1, p_xm, init_query, b1,
                                             rmean, rvar, gamma, beta,
                                             p_h, DD2, DD2);
    // 5) out = W2 @ g_h + b2
    gemm_kernel<0><<<dim3(16, 4, BB), 256>>>(W2, p_h, nullptr, b2,
                                             nullptr, nullptr, nullptr, nullptr,
                                             out, DD, DD2);
}

// round 6
// speedup vs baseline: 2.0476x; 2.0476x over previous
#include <cuda_runtime.h>
#include <cuda_bf16.h>
#include <math.h>
#include <float.h>
#include <stdint.h>

// Problem constants
#define BB   2
#define DD   512
#define NN   2048
#define HH   8
#define DD2  1024
#define EPSV 1e-5f

// ---------------------------------------------------------------------------
// Scratch
// ---------------------------------------------------------------------------
__device__ float g_q [BB * DD  * NN];
__device__ float g_k [BB * DD  * NN];
__device__ float g_v [BB * DD  * NN];
__device__ float g_x [BB * DD  * NN];
__device__ float g_xm[BB * DD  * NN];
__device__ float g_h [BB * DD2 * NN];
__device__ unsigned long long g_mbits[BB * NN * 32];  // 1 MB bitmask

// ---------------------------------------------------------------------------
// Helpers
// ---------------------------------------------------------------------------
__device__ __forceinline__ uint32_t pk2(float lo, float hi) {
    // pack: lower 16 bits = bf16(lo), upper = bf16(hi)
    uint32_t r;
    asm("cvt.rn.bf16x2.f32 %0, %1, %2;" : "=r"(r) : "f"(hi), "f"(lo));
    return r;
}
__device__ __forceinline__ float bf16val(float x) {
    return __bfloat162float(__float2bfloat16_rn(x));
}
__device__ __forceinline__ void mma16816(float c[4], const uint32_t a[4], const uint32_t b[2]) {
    asm volatile(
        "mma.sync.aligned.m16n8k16.row.col.f32.bf16.bf16.f32 "
        "{%0,%1,%2,%3}, {%4,%5,%6,%7}, {%8,%9}, {%0,%1,%2,%3};"
        : "+f"(c[0]), "+f"(c[1]), "+f"(c[2]), "+f"(c[3])
        : "r"(a[0]), "r"(a[1]), "r"(a[2]), "r"(a[3]), "r"(b[0]), "r"(b[1]));
}

// ---------------------------------------------------------------------------
// Mask -> bitmask pre-kernel. word (b, r, w) covers key cols w*64..w*64+63.
// ---------------------------------------------------------------------------
__global__ void maskbits_kernel(const int* __restrict__ mask)
{
    const int idx = blockIdx.x * 256 + threadIdx.x;   // BB*NN*32 = 131072
    const int b = idx >> 16;                          // NN*32 = 65536
    const int r = (idx >> 5) & (NN - 1);
    const int w = idx & 31;
    const int4* mp = (const int4*)(mask + ((size_t)b * NN + r) * NN + w * 64);
    unsigned long long bits = 0ULL;
#pragma unroll
    for (int i = 0; i < 16; ++i) {
        const int4 m4 = mp[i];
        bits |= (unsigned long long)(m4.x != 0) << (4 * i + 0);
        bits |= (unsigned long long)(m4.y != 0) << (4 * i + 1);
        bits |= (unsigned long long)(m4.z != 0) << (4 * i + 2);
        bits |= (unsigned long long)(m4.w != 0) << (4 * i + 3);
    }
    g_mbits[idx] = bits;
}

// ---------------------------------------------------------------------------
// Tensor-core GEMM: out (O x N) = W (O x I) @ X (I x N) + bias
// CTA 128x128, K-step 32, 256 threads = 8 warps (2m x 4n), warp tile 64x32.
// 3xBF16 split precision (hi*hi + hi*lo + lo*hi).
// MODE 1: concat rows [0,512)=X, [512,1024)=X2; BN + ReLU epilogue.
// ---------------------------------------------------------------------------
template <int MODE>
__device__ __forceinline__ void gemm_body_tc(
    const float* __restrict__ W, const float* __restrict__ X,
    const float* __restrict__ X2, const float* __restrict__ bias,
    const float* __restrict__ rmean, const float* __restrict__ rvar,
    const float* __restrict__ gam,   const float* __restrict__ bet,
    float* __restrict__ out, int O, int I)
{
    __shared__ uint32_t AsH[128][20], AsL[128][20];   // [o][kp] packed k pairs
    __shared__ uint32_t BsH[16][136], BsL[16][136];   // [kp][n] packed k pairs

    const int tid  = threadIdx.x;
    const int lane = tid & 31, warp = tid >> 5;
    const int g = lane >> 2, tg = lane & 3;
    const int n0 = blockIdx.x * 128, o0 = blockIdx.y * 128;
    const int wm = (warp >> 2) * 64;
    const int wn = (warp & 3) * 32;

    float acc[4][4][4];
#pragma unroll
    for (int mi = 0; mi < 4; ++mi)
#pragma unroll
        for (int ni = 0; ni < 4; ++ni)
#pragma unroll
            for (int t = 0; t < 4; ++t) acc[mi][ni][t] = 0.f;

    for (int k0 = 0; k0 < I; k0 += 32) {
        // --- A loader: W tile 128 x 32 ---
#pragma unroll
        for (int s = 0; s < 4; ++s) {
            const int u = tid + s * 256;
            const int o = u >> 3;
            const int kc = (u & 7) << 2;
            const float4 w4 = *(const float4*)(W + (size_t)(o0 + o) * I + k0 + kc);
            const float hx = bf16val(w4.x), hy = bf16val(w4.y);
            const float hz = bf16val(w4.z), hw = bf16val(w4.w);
            *(uint2*)&AsH[o][kc >> 1] = make_uint2(pk2(hx, hy), pk2(hz, hw));
            *(uint2*)&AsL[o][kc >> 1] =
                make_uint2(pk2(w4.x - hx, w4.y - hy), pk2(w4.z - hz, w4.w - hw));
        }
        // --- B loader: X tile 32 x 128, pack along k pairs ---
#pragma unroll
        for (int s = 0; s < 2; ++s) {
            const int u = tid + s * 256;
            const int kp = u >> 5;
            const int nc = (u & 31) << 2;
            const int row0 = k0 + kp * 2;
            const float *s0, *s1;
            if (MODE == 1) {
                s0 = (row0 < DD) ? (X + (size_t)row0 * NN) : (X2 + (size_t)(row0 - DD) * NN);
                const int row1 = row0 + 1;
                s1 = (row1 < DD) ? (X + (size_t)row1 * NN) : (X2 + (size_t)(row1 - DD) * NN);
            } else {
                s0 = X + (size_t)row0 * NN;
                s1 = s0 + NN;
            }
            const float4 x0 = *(const float4*)(s0 + n0 + nc);
            const float4 x1 = *(const float4*)(s1 + n0 + nc);
            const float h0x = bf16val(x0.x), h0y = bf16val(x0.y),
                        h0z = bf16val(x0.z), h0w = bf16val(x0.w);
            const float h1x = bf16val(x1.x), h1y = bf16val(x1.y),
                        h1z = bf16val(x1.z), h1w = bf16val(x1.w);
            uint4 hv, lv;
            hv.x = pk2(h0x, h1x); hv.y = pk2(h0y, h1y);
            hv.z = pk2(h0z, h1z); hv.w = pk2(h0w, h1w);
            lv.x = pk2(x0.x - h0x, x1.x - h1x); lv.y = pk2(x0.y - h0y, x1.y - h1y);
            lv.z = pk2(x0.z - h0z, x1.z - h1z); lv.w = pk2(x0.w - h0w, x1.w - h1w);
            *(uint4*)&BsH[kp][nc] = hv;
            *(uint4*)&BsL[kp][nc] = lv;
        }
        __syncthreads();

#pragma unroll
        for (int ks = 0; ks < 2; ++ks) {
            const int kb = ks * 8;
            uint32_t ah[4][4], al[4][4];
#pragma unroll
            for (int mi = 0; mi < 4; ++mi) {
                const int r0 = wm + mi * 16 + g;
                ah[mi][0] = AsH[r0][kb + tg];     ah[mi][1] = AsH[r0 + 8][kb + tg];
                ah[mi][2] = AsH[r0][kb + tg + 4]; ah[mi][3] = AsH[r0 + 8][kb + tg + 4];
                al[mi][0] = AsL[r0][kb + tg];     al[mi][1] = AsL[r0 + 8][kb + tg];
                al[mi][2] = AsL[r0][kb + tg + 4]; al[mi][3] = AsL[r0 + 8][kb + tg + 4];
            }
#pragma unroll
            for (int ni = 0; ni < 4; ++ni) {
                const int c0 = wn + ni * 8 + g;
                uint32_t bh[2] = { BsH[kb + tg][c0], BsH[kb + tg + 4][c0] };
                uint32_t bl[2] = { BsL[kb + tg][c0], BsL[kb + tg + 4][c0] };
#pragma unroll
                for (int mi = 0; mi < 4; ++mi) {
                    mma16816(acc[mi][ni], ah[mi], bh);
                    mma16816(acc[mi][ni], ah[mi], bl);
                    mma16816(acc[mi][ni], al[mi], bh);
                }
            }
        }
        __syncthreads();
    }

    // --- epilogue ---
#pragma unroll
    for (int mi = 0; mi < 4; ++mi) {
#pragma unroll
        for (int rr = 0; rr < 2; ++rr) {
            const int o = o0 + wm + mi * 16 + rr * 8 + g;
            const float bi = bias[o];
            float sc = 1.f, sh = bi;
            if (MODE == 1) {
                const float s = gam[o] * rsqrtf(rvar[o] + EPSV);
                sc = s;
                sh = (bi - rmean[o]) * s + bet[o];
            }
#pragma unroll
            for (int ni = 0; ni < 4; ++ni) {
                float v0 = acc[mi][ni][rr * 2 + 0] * sc + sh;
                float v1 = acc[mi][ni][rr * 2 + 1] * sc + sh;
                if (MODE == 1) { v0 = fmaxf(v0, 0.f); v1 = fmaxf(v1, 0.f); }
                *(float2*)(out + (size_t)o * NN + n0 + wn + ni * 8 + tg * 2) =
                    make_float2(v0, v1);
            }
        }
    }
}

__global__ __launch_bounds__(256)
void qkv_kernel(const float* __restrict__ xq, const float* __restrict__ xk,
                const float* __restrict__ xv,
                const float* __restrict__ Wq, const float* __restrict__ bq,
                const float* __restrict__ Wk, const float* __restrict__ bk,
                const float* __restrict__ Wv, const float* __restrict__ bv)
{
    const int z = blockIdx.z, b = z & 1, sel = z >> 1;
    const float *W, *X, *bi;
    float* outp;
    if (sel == 0)      { W = Wq; X = xq; bi = bq; outp = g_q; }
    else if (sel == 1) { W = Wk; X = xk; bi = bk; outp = g_k; }
    else               { W = Wv; X = xv; bi = bv; outp = g_v; }
    gemm_body_tc<0>(W, X + (size_t)b * DD * NN, nullptr, bi,
                    nullptr, nullptr, nullptr, nullptr,
                    outp + (size_t)b * DD * NN, DD, DD);
}

template <int MODE>
__global__ __launch_bounds__(256)
void gemm_kernel(const float* __restrict__ W, const float* __restrict__ X,
                 const float* __restrict__ X2, const float* __restrict__ bias,
                 const float* __restrict__ rmean, const float* __restrict__ rvar,
                 const float* __restrict__ gam,   const float* __restrict__ bet,
                 float* __restrict__ out, int O, int I)
{
    const int b = blockIdx.z;
    const size_t xs = (MODE == 1) ? (size_t)DD * NN : (size_t)I * NN;
    gemm_body_tc<MODE>(W, X + (size_t)b * xs,
                       (MODE == 1) ? (X2 + (size_t)b * DD * NN) : nullptr,
                       bias, rmean, rvar, gam, bet,
                       out + (size_t)b * O * NN, O, I);
}

// ---------------------------------------------------------------------------
// Tensor-core flash attention. CTA: 64 query rows x one (b,h); 128 threads =
// 4 warps, warp = 16 query rows. Key tiles of 64, online softmax in registers,
// P fragments feed P@V mma directly. 3xBF16 split on both GEMMs.
// ---------------------------------------------------------------------------
#define ATT_SMEM (2304 * 6 * 4)   // 6 planes of 2304 uint32 = 55296 B

__global__ __launch_bounds__(128)
void attn_tc_kernel()
{
    extern __shared__ uint32_t smu[];
    uint32_t* QH = smu;              // [64][36] A-planes (pack along dk)
    uint32_t* QL = QH + 2304;
    uint32_t* KH = QL + 2304;        // [32][72] B-planes (pack along dk)
    uint32_t* KL = KH + 2304;
    uint32_t* VH = KL + 2304;        // [32][72] B-planes (pack along c)
    uint32_t* VL = VH + 2304;

    const int tid  = threadIdx.x;
    const int lane = tid & 31, warp = tid >> 5;
    const int g = lane >> 2, tg = lane & 3;
    const int b = blockIdx.z, h = blockIdx.y, n0 = blockIdx.x * 64;
    const int rb = warp * 16;

    // --- load Q tile (64 dk x 64 r), packed pairs along dk ---
#pragma unroll
    for (int s = 0; s < 4; ++s) {
        const int u = tid + s * 128;
        const int dkp = u >> 4;
        const int rc  = (u & 15) << 2;
        const float* q0 = g_q + ((size_t)b * DD + (size_t)(2 * dkp) * HH + h) * NN + n0 + rc;
        const float4 x0 = *(const float4*)q0;
        const float4 x1 = *(const float4*)(q0 + (size_t)HH * NN);
        float ha, hb;
        ha = bf16val(x0.x); hb = bf16val(x1.x);
        QH[(rc + 0) * 36 + dkp] = pk2(ha, hb);
        QL[(rc + 0) * 36 + dkp] = pk2(x0.x - ha, x1.x - hb);
        ha = bf16val(x0.y); hb = bf16val(x1.y);
        QH[(rc + 1) * 36 + dkp] = pk2(ha, hb);
        QL[(rc + 1) * 36 + dkp] = pk2(x0.y - ha, x1.y - hb);
        ha = bf16val(x0.z); hb = bf16val(x1.z);
        QH[(rc + 2) * 36 + dkp] = pk2(ha, hb);
        QL[(rc + 2) * 36 + dkp] = pk2(x0.z - ha, x1.z - hb);
        ha = bf16val(x0.w); hb = bf16val(x1.w);
        QH[(rc + 3) * 36 + dkp] = pk2(ha, hb);
        QL[(rc + 3) * 36 + dkp] = pk2(x0.w - ha, x1.w - hb);
    }

    float oacc[8][4];
#pragma unroll
    for (int ni = 0; ni < 8; ++ni)
#pragma unroll
        for (int t = 0; t < 4; ++t) oacc[ni][t] = 0.f;
    float mrow0 = -INFINITY, mrow8 = -INFINITY, lrow0 = 0.f, lrow8 = 0.f;

    const size_t mrowbase0 = ((size_t)b * NN + n0 + rb + g) * 32;
    const size_t mrowbase8 = mrowbase0 + 8 * 32;

    for (int m0 = 0; m0 < NN; m0 += 64) {
        __syncthreads();
        // --- load K tile (pack pairs along dk) ---
#pragma unroll
        for (int s = 0; s < 4; ++s) {
            const int u = tid + s * 128;
            const int dkp = u >> 4;
            const int cc  = (u & 15) << 2;
            const float* kp0 = g_k + ((size_t)b * DD + (size_t)(2 * dkp) * HH + h) * NN + m0 + cc;
            const float4 x0 = *(const float4*)kp0;
            const float4 x1 = *(const float4*)(kp0 + (size_t)HH * NN);
            const float hx0 = bf16val(x0.x), hy0 = bf16val(x0.y),
                        hz0 = bf16val(x0.z), hw0 = bf16val(x0.w);
            const float hx1 = bf16val(x1.x), hy1 = bf16val(x1.y),
                        hz1 = bf16val(x1.z), hw1 = bf16val(x1.w);
            uint4 hv, lv;
            hv.x = pk2(hx0, hx1); hv.y = pk2(hy0, hy1);
            hv.z = pk2(hz0, hz1); hv.w = pk2(hw0, hw1);
            lv.x = pk2(x0.x - hx0, x1.x - hx1); lv.y = pk2(x0.y - hy0, x1.y - hy1);
            lv.z = pk2(x0.z - hz0, x1.z - hz1); lv.w = pk2(x0.w - hw0, x1.w - hw1);
            *(uint4*)&KH[dkp * 72 + cc] = hv;
            *(uint4*)&KL[dkp * 72 + cc] = lv;
        }
        // --- load V tile (pack pairs along c) ---
#pragma unroll
        for (int s = 0; s < 8; ++s) {
            const int u = tid + s * 128;
            const int dk = u >> 4;
            const int cc = (u & 15) << 2;
            const float* vp = g_v + ((size_t)b * DD + (size_t)dk * HH + h) * NN + m0 + cc;
            const float4 x = *(const float4*)vp;
            const float hx = bf16val(x.x), hy = bf16val(x.y),
                        hz = bf16val(x.z), hw = bf16val(x.w);
            const int cp = cc >> 1;
            VH[(cp + 0) * 72 + dk] = pk2(hx, hy);
            VH[(cp + 1) * 72 + dk] = pk2(hz, hw);
            VL[(cp + 0) * 72 + dk] = pk2(x.x - hx, x.y - hy);
            VL[(cp + 1) * 72 + dk] = pk2(x.z - hz, x.w - hw);
        }
        __syncthreads();

        // --- S = Q K^T (3x split) ---
        float sv[8][4];
#pragma unroll
        for (int ni = 0; ni < 8; ++ni)
#pragma unroll
            for (int t = 0; t < 4; ++t) sv[ni][t] = 0.f;
#pragma unroll
        for (int ks = 0; ks < 4; ++ks) {
            const int kb = ks * 8;
            const int r0 = rb + g;
            uint32_t qh[4], ql[4];
            qh[0] = QH[r0 * 36 + kb + tg];           qh[1] = QH[(r0 + 8) * 36 + kb + tg];
            qh[2] = QH[r0 * 36 + kb + tg + 4];       qh[3] = QH[(r0 + 8) * 36 + kb + tg + 4];
            ql[0] = QL[r0 * 36 + kb + tg];           ql[1] = QL[(r0 + 8) * 36 + kb + tg];
            ql[2] = QL[r0 * 36 + kb + tg + 4];       ql[3] = QL[(r0 + 8) * 36 + kb + tg + 4];
#pragma unroll
            for (int ni = 0; ni < 8; ++ni) {
                const int c0 = ni * 8 + g;
                uint32_t bh[2] = { KH[(kb + tg) * 72 + c0], KH[(kb + tg + 4) * 72 + c0] };
                uint32_t bl[2] = { KL[(kb + tg) * 72 + c0], KL[(kb + tg + 4) * 72 + c0] };
                mma16816(sv[ni], qh, bh);
                mma16816(sv[ni], qh, bl);
                mma16816(sv[ni], ql, bh);
            }
        }

        // --- mask + scale ---
        const unsigned long long w0 = g_mbits[mrowbase0 + (m0 >> 6)];
        const unsigned long long w8 = g_mbits[mrowbase8 + (m0 >> 6)];
#pragma unroll
        for (int ni = 0; ni < 8; ++ni) {
            const int cb = ni * 8 + tg * 2;
            sv[ni][0] = ((w0 >> cb) & 1ULL)       ? sv[ni][0] * 0.125f : -1e9f;
            sv[ni][1] = ((w0 >> (cb + 1)) & 1ULL) ? sv[ni][1] * 0.125f : -1e9f;
            sv[ni][2] = ((w8 >> cb) & 1ULL)       ? sv[ni][2] * 0.125f : -1e9f;
            sv[ni][3] = ((w8 >> (cb + 1)) & 1ULL) ? sv[ni][3] * 0.125f : -1e9f;
        }

        // --- online softmax (rows g and g+8, reduce across tg quad) ---
        float mx0 = -INFINITY, mx8 = -INFINITY;
#pragma unroll
        for (int ni = 0; ni < 8; ++ni) {
            mx0 = fmaxf(mx0, fmaxf(sv[ni][0], sv[ni][1]));
            mx8 = fmaxf(mx8, fmaxf(sv[ni][2], sv[ni][3]));
        }
        mx0 = fmaxf(mx0, __shfl_xor_sync(0xffffffffu, mx0, 1));
        mx0 = fmaxf(mx0, __shfl_xor_sync(0xffffffffu, mx0, 2));
        mx8 = fmaxf(mx8, __shfl_xor_sync(0xffffffffu, mx8, 1));
        mx8 = fmaxf(mx8, __shfl_xor_sync(0xffffffffu, mx8, 2));
        const float mn0 = fmaxf(mrow0, mx0), mn8 = fmaxf(mrow8, mx8);
        const float al0 = __expf(mrow0 - mn0), al8 = __expf(mrow8 - mn8);
        mrow0 = mn0; mrow8 = mn8;
        float sum0 = 0.f, sum8 = 0.f;
#pragma unroll
        for (int ni = 0; ni < 8; ++ni) {
            sv[ni][0] = __expf(sv[ni][0] - mn0); sum0 += sv[ni][0];
            sv[ni][1] = __expf(sv[ni][1] - mn0); sum0 += sv[ni][1];
            sv[ni][2] = __expf(sv[ni][2] - mn8); sum8 += sv[ni][2];
            sv[ni][3] = __expf(sv[ni][3] - mn8); sum8 += sv[ni][3];
        }
        sum0 += __shfl_xor_sync(0xffffffffu, sum0, 1);
        sum0 += __shfl_xor_sync(0xffffffffu, sum0, 2);
        sum8 += __shfl_xor_sync(0xffffffffu, sum8, 1);
        sum8 += __shfl_xor_sync(0xffffffffu, sum8, 2);
        lrow0 = lrow0 * al0 + sum0;
        lrow8 = lrow8 * al8 + sum8;
#pragma unroll
        for (int ni = 0; ni < 8; ++ni) {
            oacc[ni][0] *= al0; oacc[ni][1] *= al0;
            oacc[ni][2] *= al8; oacc[ni][3] *= al8;
        }

        // --- pack P (register C-frags -> A-frags), hi/lo split ---
        uint32_t ph01[8], pl01[8], ph23[8], pl23[8];
#pragma unroll
        for (int ni = 0; ni < 8; ++ni) {
            const float h0 = bf16val(sv[ni][0]), h1 = bf16val(sv[ni][1]);
            ph01[ni] = pk2(h0, h1);
            pl01[ni] = pk2(sv[ni][0] - h0, sv[ni][1] - h1);
            const float h2 = bf16val(sv[ni][2]), h3 = bf16val(sv[ni][3]);
            ph23[ni] = pk2(h2, h3);
            pl23[ni] = pk2(sv[ni][2] - h2, sv[ni][3] - h3);
        }

        // --- O += P V (3x split) ---
#pragma unroll
        for (int j = 0; j < 4; ++j) {
            const int kb = j * 8;
            uint32_t ah[4]  = { ph01[2 * j], ph23[2 * j], ph01[2 * j + 1], ph23[2 * j + 1] };
            uint32_t alr[4] = { pl01[2 * j], pl23[2 * j], pl01[2 * j + 1], pl23[2 * j + 1] };
#pragma unroll
            for (int ni = 0; ni < 8; ++ni) {
                const int c0 = ni * 8 + g;
                uint32_t bh[2] = { VH[(kb + tg) * 72 + c0], VH[(kb + tg + 4) * 72 + c0] };
                uint32_t bl[2] = { VL[(kb + tg) * 72 + c0], VL[(kb + tg + 4) * 72 + c0] };
                mma16816(oacc[ni], ah, bh);
                mma16816(oacc[ni], ah, bl);
                mma16816(oacc[ni], alr, bh);
            }
        }
    }
    __syncthreads();

    // --- epilogue: normalize, stage per-warp [64 dk][17], coalesced store ---
    const float inv0 = 1.f / lrow0, inv8 = 1.f / lrow8;
    float* os = (float*)smu + warp * (64 * 17);
#pragma unroll
    for (int ni = 0; ni < 8; ++ni) {
        const int dk0 = ni * 8 + tg * 2;
        os[(dk0 + 0) * 17 + g]     = oacc[ni][0] * inv0;
        os[(dk0 + 1) * 17 + g]     = oacc[ni][1] * inv0;
        os[(dk0 + 0) * 17 + 8 + g] = oacc[ni][2] * inv8;
        os[(dk0 + 1) * 17 + 8 + g] = oacc[ni][3] * inv8;
    }
    __syncwarp();
#pragma unroll
    for (int t = 0; t < 2; ++t) {
        const int dk = lane * 2 + t;
        float* dst = g_x + ((size_t)b * DD + (size_t)dk * HH + h) * NN + n0 + rb;
        const float* src = os + dk * 17;
#pragma unroll
        for (int q4 = 0; q4 < 4; ++q4)
            *(float4*)(dst + q4 * 4) =
                make_float4(src[q4 * 4], src[q4 * 4 + 1], src[q4 * 4 + 2], src[q4 * 4 + 3]);
    }
}

// ---------------------------------------------------------------------------
// Launch
// ---------------------------------------------------------------------------
extern "C" void kernel_launch(void* const* d_in, const int* in_sizes, int n_in,
                              void* d_out, int out_size)
{
    const float* init_query = (const float*)d_in[0];
    const float* key_t      = (const float*)d_in[1];
    const float* value      = (const float*)d_in[2];
    const int*   mask       = (const int*)  d_in[3];
    const float* Wq    = (const float*)d_in[4];
    const float* bq    = (const float*)d_in[5];
    const float* Wk    = (const float*)d_in[6];
    const float* bk    = (const float*)d_in[7];
    const float* Wv    = (const float*)d_in[8];
    const float* bv    = (const float*)d_in[9];
    const float* Wm    = (const float*)d_in[10];
    const float* bm    = (const float*)d_in[11];
    const float* W1    = (const float*)d_in[12];
    const float* b1    = (const float*)d_in[13];
    const float* gamma = (const float*)d_in[14];
    const float* beta  = (const float*)d_in[15];
    const float* rmean = (const float*)d_in[16];
    const float* rvar  = (const float*)d_in[17];
    const float* W2    = (const float*)d_in[18];
    const float* b2    = (const float*)d_in[19];
    float* out = (float*)d_out;

    float *p_x, *p_xm, *p_h;
    cudaGetSymbolAddress((void**)&p_x,  g_x);
    cudaGetSymbolAddress((void**)&p_xm, g_xm);
    cudaGetSymbolAddress((void**)&p_h,  g_h);

    cudaFuncSetAttribute(attn_tc_kernel,
                         cudaFuncAttributeMaxDynamicSharedMemorySize, ATT_SMEM);

    // 0) mask -> bitmask (1 MB, lives in L2)
    maskbits_kernel<<<512, 256>>>(mask);
    // 1) q/k/v projections
    qkv_kernel<<<dim3(16, 4, 6), 256>>>(init_query, key_t, value,
                                        Wq, bq, Wk, bk, Wv, bv);
    // 2) flash attention -> g_x
    attn_tc_kernel<<<dim3(NN / 64, HH, BB), 128, ATT_SMEM>>>();
    // 3) merge conv
    gemm_kernel<0><<<dim3(16, 4, BB), 256>>>(Wm, p_x, nullptr, bm,
                                             nullptr, nullptr, nullptr, nullptr,
                                             p_xm, DD, DD);
    // 4) W1 @ [xm ; init_query] + BN + ReLU
    gemm_kernel<1><<<dim3(16, 8, BB), 256>>>(W1, p_xm, init_query, b1,
                                             rmean, rvar, gamma, beta,
                                             p_h, DD2, DD2);
    // 5) out = W2 @ h + b2
    gemm_kernel<0><<<dim3(16, 4, BB), 256>>>(W2, p_h, nullptr, b2,
                                             nullptr, nullptr, nullptr, nullptr,
                                             out, DD, DD2);
}

// round 7
// speedup vs baseline: 2.3699x; 1.1574x over previous
#include <cuda_runtime.h>
#include <cuda_bf16.h>
#include <math.h>
#include <float.h>
#include <stdint.h>

// Problem constants
#define BB   2
#define DD   512
#define NN   2048
#define HH   8
#define DD2  1024
#define EPSV 1e-5f

// ---------------------------------------------------------------------------
// Scratch
// ---------------------------------------------------------------------------
__device__ float g_q [BB * DD  * NN];
__device__ float g_k [BB * DD  * NN];
__device__ float g_v [BB * DD  * NN];
__device__ float g_x [BB * DD  * NN];
__device__ float g_xm[BB * DD  * NN];
__device__ float g_h [BB * DD2 * NN];
__device__ unsigned long long g_mbits[BB * NN * 32];  // 1 MB bitmask

// ---------------------------------------------------------------------------
// Helpers
// ---------------------------------------------------------------------------
__device__ __forceinline__ uint32_t pk2(float lo, float hi) {
    uint32_t r;
    asm("cvt.rn.bf16x2.f32 %0, %1, %2;" : "=r"(r) : "f"(hi), "f"(lo));
    return r;
}
__device__ __forceinline__ float bf16val(float x) {
    return __bfloat162float(__float2bfloat16_rn(x));
}
__device__ __forceinline__ void mma16816(float c[4], const uint32_t a[4], const uint32_t b[2]) {
    asm volatile(
        "mma.sync.aligned.m16n8k16.row.col.f32.bf16.bf16.f32 "
        "{%0,%1,%2,%3}, {%4,%5,%6,%7}, {%8,%9}, {%0,%1,%2,%3};"
        : "+f"(c[0]), "+f"(c[1]), "+f"(c[2]), "+f"(c[3])
        : "r"(a[0]), "r"(a[1]), "r"(a[2]), "r"(a[3]), "r"(b[0]), "r"(b[1]));
}

// ---------------------------------------------------------------------------
// Mask -> bitmask pre-kernel. word (b, r, w) covers key cols w*64..w*64+63.
// ---------------------------------------------------------------------------
__global__ void maskbits_kernel(const int* __restrict__ mask)
{
    const int idx = blockIdx.x * 256 + threadIdx.x;   // BB*NN*32 = 131072
    const int b = idx >> 16;
    const int r = (idx >> 5) & (NN - 1);
    const int w = idx & 31;
    const int4* mp = (const int4*)(mask + ((size_t)b * NN + r) * NN + w * 64);
    unsigned long long bits = 0ULL;
#pragma unroll
    for (int i = 0; i < 16; ++i) {
        const int4 m4 = mp[i];
        bits |= (unsigned long long)(m4.x != 0) << (4 * i + 0);
        bits |= (unsigned long long)(m4.y != 0) << (4 * i + 1);
        bits |= (unsigned long long)(m4.z != 0) << (4 * i + 2);
        bits |= (unsigned long long)(m4.w != 0) << (4 * i + 3);
    }
    g_mbits[idx] = bits;
}

// ---------------------------------------------------------------------------
// Tensor-core GEMM with 2-stage smem double buffer + register prefetch.
// out (O x N) = W (O x I) @ X (I x N) + bias; CTA 128x128, k-step 32.
// 3xBF16 split precision. MODE 1: concat B rows + BN + ReLU.
// Dynamic smem: 2 stages x (AH 2560 | AL 2560 | BH 2112 | BL 2112) words.
// ---------------------------------------------------------------------------
#define GW_STAGE 9344
#define GEMM_SMEM (2 * GW_STAGE * 4)

template <int MODE>
__device__ __forceinline__ void gemm_body_tc(
    const float* __restrict__ W, const float* __restrict__ X,
    const float* __restrict__ X2, const float* __restrict__ bias,
    const float* __restrict__ rmean, const float* __restrict__ rvar,
    const float* __restrict__ gam,   const float* __restrict__ bet,
    float* __restrict__ out, int O, int I)
{
    extern __shared__ uint32_t gsm[];

    const int tid  = threadIdx.x;
    const int lane = tid & 31, warp = tid >> 5;
    const int g = lane >> 2, tg = lane & 3;
    const int n0 = blockIdx.x * 128, o0 = blockIdx.y * 128;
    const int wm = (warp >> 2) * 64;
    const int wn = (warp & 3) * 32;

    float acc[4][4][4];
#pragma unroll
    for (int mi = 0; mi < 4; ++mi)
#pragma unroll
        for (int ni = 0; ni < 4; ++ni)
#pragma unroll
            for (int t = 0; t < 4; ++t) acc[mi][ni][t] = 0.f;

    float4 pa[4], pbx0[2], pbx1[2];

#define G_LDG(K0) do {                                                         \
    _Pragma("unroll")                                                          \
    for (int s = 0; s < 4; ++s) {                                              \
        const int u = tid + s * 256;                                           \
        const int o = u >> 3;                                                  \
        const int kc = (u & 7) << 2;                                           \
        pa[s] = *(const float4*)(W + (size_t)(o0 + o) * I + (K0) + kc);        \
    }                                                                          \
    _Pragma("unroll")                                                          \
    for (int s = 0; s < 2; ++s) {                                              \
        const int u = tid + s * 256;                                           \
        const int kp = u >> 5;                                                 \
        const int nc = (u & 31) << 2;                                          \
        const int row0 = (K0) + kp * 2;                                        \
        const float *s0p, *s1p;                                                \
        if (MODE == 1) {                                                       \
            s0p = (row0 < DD) ? (X + (size_t)row0 * NN)                        \
                              : (X2 + (size_t)(row0 - DD) * NN);               \
            const int row1 = row0 + 1;                                         \
            s1p = (row1 < DD) ? (X + (size_t)row1 * NN)                        \
                              : (X2 + (size_t)(row1 - DD) * NN);               \
        } else {                                                               \
            s0p = X + (size_t)row0 * NN;                                       \
            s1p = s0p + NN;                                                    \
        }                                                                      \
        pbx0[s] = *(const float4*)(s0p + n0 + nc);                             \
        pbx1[s] = *(const float4*)(s1p + n0 + nc);                             \
    } } while (0)

#define G_STS(ST) do {                                                         \
    uint32_t* AHp = gsm + (ST) * GW_STAGE;                                     \
    uint32_t* ALp = AHp + 2560;                                                \
    uint32_t* BHp = AHp + 5120;                                                \
    uint32_t* BLp = AHp + 7232;                                                \
    _Pragma("unroll")                                                          \
    for (int s = 0; s < 4; ++s) {                                              \
        const int u = tid + s * 256;                                           \
        const int o = u >> 3;                                                  \
        const int kc = (u & 7) << 2;                                           \
        const float4 w4 = pa[s];                                               \
        const float hx = bf16val(w4.x), hy = bf16val(w4.y);                    \
        const float hz = bf16val(w4.z), hw = bf16val(w4.w);                    \
        *(uint2*)&AHp[o * 20 + (kc >> 1)] = make_uint2(pk2(hx, hy), pk2(hz, hw)); \
        *(uint2*)&ALp[o * 20 + (kc >> 1)] =                                    \
            make_uint2(pk2(w4.x - hx, w4.y - hy), pk2(w4.z - hz, w4.w - hw));  \
    }                                                                          \
    _Pragma("unroll")                                                          \
    for (int s = 0; s < 2; ++s) {                                              \
        const int u = tid + s * 256;                                           \
        const int kp = u >> 5;                                                 \
        const int nc = (u & 31) << 2;                                          \
        const float4 x0 = pbx0[s], x1 = pbx1[s];                               \
        const float h0x = bf16val(x0.x), h0y = bf16val(x0.y),                  \
                    h0z = bf16val(x0.z), h0w = bf16val(x0.w);                  \
        const float h1x = bf16val(x1.x), h1y = bf16val(x1.y),                  \
                    h1z = bf16val(x1.z), h1w = bf16val(x1.w);                  \
        uint4 hv, lv;                                                          \
        hv.x = pk2(h0x, h1x); hv.y = pk2(h0y, h1y);                            \
        hv.z = pk2(h0z, h1z); hv.w = pk2(h0w, h1w);                            \
        lv.x = pk2(x0.x - h0x, x1.x - h1x); lv.y = pk2(x0.y - h0y, x1.y - h1y);\
        lv.z = pk2(x0.z - h0z, x1.z - h1z); lv.w = pk2(x0.w - h0w, x1.w - h1w);\
        *(uint4*)&BHp[kp * 132 + nc] = hv;                                     \
        *(uint4*)&BLp[kp * 132 + nc] = lv;                                     \
    } } while (0)

    const int T = I / 32;
    G_LDG(0);
    G_STS(0);
    G_LDG(32);
    __syncthreads();

    for (int t = 0; t < T; ++t) {
        const uint32_t* AHp = gsm + (t & 1) * GW_STAGE;
        const uint32_t* ALp = AHp + 2560;
        const uint32_t* BHp = AHp + 5120;
        const uint32_t* BLp = AHp + 7232;
#pragma unroll
        for (int ks = 0; ks < 2; ++ks) {
            const int kb = ks * 8;
            uint32_t ah[4][4], al[4][4];
#pragma unroll
            for (int mi = 0; mi < 4; ++mi) {
                const int r0 = wm + mi * 16 + g;
                ah[mi][0] = AHp[r0 * 20 + kb + tg];
                ah[mi][1] = AHp[(r0 + 8) * 20 + kb + tg];
                ah[mi][2] = AHp[r0 * 20 + kb + tg + 4];
                ah[mi][3] = AHp[(r0 + 8) * 20 + kb + tg + 4];
                al[mi][0] = ALp[r0 * 20 + kb + tg];
                al[mi][1] = ALp[(r0 + 8) * 20 + kb + tg];
                al[mi][2] = ALp[r0 * 20 + kb + tg + 4];
                al[mi][3] = ALp[(r0 + 8) * 20 + kb + tg + 4];
            }
#pragma unroll
            for (int ni = 0; ni < 4; ++ni) {
                const int c0 = wn + ni * 8 + g;
                uint32_t bh[2] = { BHp[(kb + tg) * 132 + c0], BHp[(kb + tg + 4) * 132 + c0] };
                uint32_t bl[2] = { BLp[(kb + tg) * 132 + c0], BLp[(kb + tg + 4) * 132 + c0] };
#pragma unroll
                for (int mi = 0; mi < 4; ++mi) {
                    mma16816(acc[mi][ni], ah[mi], bh);
                    mma16816(acc[mi][ni], ah[mi], bl);
                    mma16816(acc[mi][ni], al[mi], bh);
                }
            }
        }
        if (t + 1 < T) {
            G_STS((t + 1) & 1);
            if (t + 2 < T) G_LDG((t + 2) * 32);
        }
        __syncthreads();
    }
#undef G_LDG
#undef G_STS

    // --- epilogue ---
#pragma unroll
    for (int mi = 0; mi < 4; ++mi) {
#pragma unroll
        for (int rr = 0; rr < 2; ++rr) {
            const int o = o0 + wm + mi * 16 + rr * 8 + g;
            const float bi = bias[o];
            float sc = 1.f, sh = bi;
            if (MODE == 1) {
                const float s = gam[o] * rsqrtf(rvar[o] + EPSV);
                sc = s;
                sh = (bi - rmean[o]) * s + bet[o];
            }
#pragma unroll
            for (int ni = 0; ni < 4; ++ni) {
                float v0 = acc[mi][ni][rr * 2 + 0] * sc + sh;
                float v1 = acc[mi][ni][rr * 2 + 1] * sc + sh;
                if (MODE == 1) { v0 = fmaxf(v0, 0.f); v1 = fmaxf(v1, 0.f); }
                *(float2*)(out + (size_t)o * NN + n0 + wn + ni * 8 + tg * 2) =
                    make_float2(v0, v1);
            }
        }
    }
}

__global__ __launch_bounds__(256)
void qkv_kernel(const float* __restrict__ xq, const float* __restrict__ xk,
                const float* __restrict__ xv,
                const float* __restrict__ Wq, const float* __restrict__ bq,
                const float* __restrict__ Wk, const float* __restrict__ bk,
                const float* __restrict__ Wv, const float* __restrict__ bv)
{
    const int z = blockIdx.z, b = z & 1, sel = z >> 1;
    const float *W, *X, *bi;
    float* outp;
    if (sel == 0)      { W = Wq; X = xq; bi = bq; outp = g_q; }
    else if (sel == 1) { W = Wk; X = xk; bi = bk; outp = g_k; }
    else               { W = Wv; X = xv; bi = bv; outp = g_v; }
    gemm_body_tc<0>(W, X + (size_t)b * DD * NN, nullptr, bi,
                    nullptr, nullptr, nullptr, nullptr,
                    outp + (size_t)b * DD * NN, DD, DD);
}

template <int MODE>
__global__ __launch_bounds__(256)
void gemm_kernel(const float* __restrict__ W, const float* __restrict__ X,
                 const float* __restrict__ X2, const float* __restrict__ bias,
                 const float* __restrict__ rmean, const float* __restrict__ rvar,
                 const float* __restrict__ gam,   const float* __restrict__ bet,
                 float* __restrict__ out, int O, int I)
{
    const int b = blockIdx.z;
    const size_t xs = (MODE == 1) ? (size_t)DD * NN : (size_t)I * NN;
    gemm_body_tc<MODE>(W, X + (size_t)b * xs,
                       (MODE == 1) ? (X2 + (size_t)b * DD * NN) : nullptr,
                       bias, rmean, rvar, gam, bet,
                       out + (size_t)b * O * NN, O, I);
}

// ---------------------------------------------------------------------------
// Tensor-core flash attention with 2-stage K/V double buffer + reg prefetch.
// CTA: 64 q-rows x (b,h), 128 threads. Smem (words):
//   QH 0..2304 | QL 2304..4608 | stage s at 4608 + s*9216:
//     KH +0 | KL +2304 | VH +4608 | VL +6912
// ---------------------------------------------------------------------------
#define AT_STAGE 9216
#define ATT_SMEM (23040 * 4)   // 92160 B

__global__ __launch_bounds__(128)
void attn_tc_kernel()
{
    extern __shared__ uint32_t smu[];
    uint32_t* QH = smu;
    uint32_t* QL = smu + 2304;

    const int tid  = threadIdx.x;
    const int lane = tid & 31, warp = tid >> 5;
    const int g = lane >> 2, tg = lane & 3;
    const int b = blockIdx.z, h = blockIdx.y, n0 = blockIdx.x * 64;
    const int rb = warp * 16;
    const int lcc = (tid & 15) << 2;     // loader column offset

    // --- load Q tile (64 dk x 64 r), packed pairs along dk ---
#pragma unroll
    for (int s = 0; s < 4; ++s) {
        const int u = tid + s * 128;
        const int dkp = u >> 4;
        const int rc  = (u & 15) << 2;
        const float* q0 = g_q + ((size_t)b * DD + (size_t)(2 * dkp) * HH + h) * NN + n0 + rc;
        const float4 x0 = *(const float4*)q0;
        const float4 x1 = *(const float4*)(q0 + (size_t)HH * NN);
        float ha, hb;
        ha = bf16val(x0.x); hb = bf16val(x1.x);
        QH[(rc + 0) * 36 + dkp] = pk2(ha, hb);
        QL[(rc + 0) * 36 + dkp] = pk2(x0.x - ha, x1.x - hb);
        ha = bf16val(x0.y); hb = bf16val(x1.y);
        QH[(rc + 1) * 36 + dkp] = pk2(ha, hb);
        QL[(rc + 1) * 36 + dkp] = pk2(x0.y - ha, x1.y - hb);
        ha = bf16val(x0.z); hb = bf16val(x1.z);
        QH[(rc + 2) * 36 + dkp] = pk2(ha, hb);
        QL[(rc + 2) * 36 + dkp] = pk2(x0.z - ha, x1.z - hb);
        ha = bf16val(x0.w); hb = bf16val(x1.w);
        QH[(rc + 3) * 36 + dkp] = pk2(ha, hb);
        QL[(rc + 3) * 36 + dkp] = pk2(x0.w - ha, x1.w - hb);
    }

    float oacc[8][4];
#pragma unroll
    for (int ni = 0; ni < 8; ++ni)
#pragma unroll
        for (int t = 0; t < 4; ++t) oacc[ni][t] = 0.f;
    float mrow0 = -INFINITY, mrow8 = -INFINITY, lrow0 = 0.f, lrow8 = 0.f;

    const size_t mrowbase0 = ((size_t)b * NN + n0 + rb + g) * 32;
    const size_t mrowbase8 = mrowbase0 + 8 * 32;

    float4 kx0[4], kx1[4], vx[8];

#define AT_LDG(M0) do {                                                        \
    _Pragma("unroll")                                                          \
    for (int s = 0; s < 4; ++s) {                                              \
        const int dkp = (tid >> 4) + s * 8;                                    \
        const float* kp0 = g_k + ((size_t)b * DD + (size_t)(2 * dkp) * HH + h) * NN + (M0) + lcc; \
        kx0[s] = *(const float4*)kp0;                                          \
        kx1[s] = *(const float4*)(kp0 + (size_t)HH * NN);                      \
    }                                                                          \
    _Pragma("unroll")                                                          \
    for (int s = 0; s < 8; ++s) {                                              \
        const int dk = (tid >> 4) + s * 8;                                     \
        vx[s] = *(const float4*)(g_v + ((size_t)b * DD + (size_t)dk * HH + h) * NN + (M0) + lcc); \
    } } while (0)

#define AT_STS(ST) do {                                                        \
    uint32_t* KHp = smu + 4608 + (ST) * AT_STAGE;                              \
    uint32_t* KLp = KHp + 2304;                                                \
    uint32_t* VHp = KHp + 4608;                                                \
    uint32_t* VLp = KHp + 6912;                                                \
    _Pragma("unroll")                                                          \
    for (int s = 0; s < 4; ++s) {                                              \
        const int dkp = (tid >> 4) + s * 8;                                    \
        const float4 x0 = kx0[s], x1 = kx1[s];                                 \
        const float hx0 = bf16val(x0.x), hy0 = bf16val(x0.y),                  \
                    hz0 = bf16val(x0.z), hw0 = bf16val(x0.w);                  \
        const float hx1 = bf16val(x1.x), hy1 = bf16val(x1.y),                  \
                    hz1 = bf16val(x1.z), hw1 = bf16val(x1.w);                  \
        uint4 hv, lv;                                                          \
        hv.x = pk2(hx0, hx1); hv.y = pk2(hy0, hy1);                            \
        hv.z = pk2(hz0, hz1); hv.w = pk2(hw0, hw1);                            \
        lv.x = pk2(x0.x - hx0, x1.x - hx1); lv.y = pk2(x0.y - hy0, x1.y - hy1);\
        lv.z = pk2(x0.z - hz0, x1.z - hz1); lv.w = pk2(x0.w - hw0, x1.w - hw1);\
        *(uint4*)&KHp[dkp * 72 + lcc] = hv;                                    \
        *(uint4*)&KLp[dkp * 72 + lcc] = lv;                                    \
    }                                                                          \
    _Pragma("unroll")                                                          \
    for (int s = 0; s < 8; ++s) {                                              \
        const int dk = (tid >> 4) + s * 8;                                     \
        const float4 x = vx[s];                                                \
        const float hx = bf16val(x.x), hy = bf16val(x.y),                      \
                    hz = bf16val(x.z), hw = bf16val(x.w);                      \
        const int cp = lcc >> 1;                                               \
        VHp[(cp + 0) * 72 + dk] = pk2(hx, hy);                                 \
        VHp[(cp + 1) * 72 + dk] = pk2(hz, hw);                                 \
        VLp[(cp + 0) * 72 + dk] = pk2(x.x - hx, x.y - hy);                     \
        VLp[(cp + 1) * 72 + dk] = pk2(x.z - hz, x.w - hw);                     \
    } } while (0)

    AT_LDG(0);
    AT_STS(0);
    AT_LDG(64);
    __syncthreads();

    for (int t = 0; t < NN / 64; ++t) {
        const int m0 = t * 64;
        const uint32_t* KHp = smu + 4608 + (t & 1) * AT_STAGE;
        const uint32_t* KLp = KHp + 2304;
        const uint32_t* VHp = KHp + 4608;
        const uint32_t* VLp = KHp + 6912;

        // --- S = Q K^T (3x split) ---
        float sv[8][4];
#pragma unroll
        for (int ni = 0; ni < 8; ++ni)
#pragma unroll
            for (int tt = 0; tt < 4; ++tt) sv[ni][tt] = 0.f;
#pragma unroll
        for (int ks = 0; ks < 4; ++ks) {
            const int kb = ks * 8;
            const int r0 = rb + g;
            uint32_t qh[4], ql[4];
            qh[0] = QH[r0 * 36 + kb + tg];       qh[1] = QH[(r0 + 8) * 36 + kb + tg];
            qh[2] = QH[r0 * 36 + kb + tg + 4];   qh[3] = QH[(r0 + 8) * 36 + kb + tg + 4];
            ql[0] = QL[r0 * 36 + kb + tg];       ql[1] = QL[(r0 + 8) * 36 + kb + tg];
            ql[2] = QL[r0 * 36 + kb + tg + 4];   ql[3] = QL[(r0 + 8) * 36 + kb + tg + 4];
#pragma unroll
            for (int ni = 0; ni < 8; ++ni) {
                const int c0 = ni * 8 + g;
                uint32_t bh[2] = { KHp[(kb + tg) * 72 + c0], KHp[(kb + tg + 4) * 72 + c0] };
                uint32_t bl[2] = { KLp[(kb + tg) * 72 + c0], KLp[(kb + tg + 4) * 72 + c0] };
                mma16816(sv[ni], qh, bh);
                mma16816(sv[ni], qh, bl);
                mma16816(sv[ni], ql, bh);
            }
        }

        // --- mask + scale ---
        const unsigned long long w0 = g_mbits[mrowbase0 + (m0 >> 6)];
        const unsigned long long w8 = g_mbits[mrowbase8 + (m0 >> 6)];
#pragma unroll
        for (int ni = 0; ni < 8; ++ni) {
            const int cb = ni * 8 + tg * 2;
            sv[ni][0] = ((w0 >> cb) & 1ULL)       ? sv[ni][0] * 0.125f : -1e9f;
            sv[ni][1] = ((w0 >> (cb + 1)) & 1ULL) ? sv[ni][1] * 0.125f : -1e9f;
            sv[ni][2] = ((w8 >> cb) & 1ULL)       ? sv[ni][2] * 0.125f : -1e9f;
            sv[ni][3] = ((w8 >> (cb + 1)) & 1ULL) ? sv[ni][3] * 0.125f : -1e9f;
        }

        // --- online softmax ---
        float mx0 = -INFINITY, mx8 = -INFINITY;
#pragma unroll
        for (int ni = 0; ni < 8; ++ni) {
            mx0 = fmaxf(mx0, fmaxf(sv[ni][0], sv[ni][1]));
            mx8 = fmaxf(mx8, fmaxf(sv[ni][2], sv[ni][3]));
        }
        mx0 = fmaxf(mx0, __shfl_xor_sync(0xffffffffu, mx0, 1));
        mx0 = fmaxf(mx0, __shfl_xor_sync(0xffffffffu, mx0, 2));
        mx8 = fmaxf(mx8, __shfl_xor_sync(0xffffffffu, mx8, 1));
        mx8 = fmaxf(mx8, __shfl_xor_sync(0xffffffffu, mx8, 2));
        const float mn0 = fmaxf(mrow0, mx0), mn8 = fmaxf(mrow8, mx8);
        const float al0 = __expf(mrow0 - mn0), al8 = __expf(mrow8 - mn8);
        mrow0 = mn0; mrow8 = mn8;
        float sum0 = 0.f, sum8 = 0.f;
#pragma unroll
        for (int ni = 0; ni < 8; ++ni) {
            sv[ni][0] = __expf(sv[ni][0] - mn0); sum0 += sv[ni][0];
            sv[ni][1] = __expf(sv[ni][1] - mn0); sum0 += sv[ni][1];
            sv[ni][2] = __expf(sv[ni][2] - mn8); sum8 += sv[ni][2];
            sv[ni][3] = __expf(sv[ni][3] - mn8); sum8 += sv[ni][3];
        }
        sum0 += __shfl_xor_sync(0xffffffffu, sum0, 1);
        sum0 += __shfl_xor_sync(0xffffffffu, sum0, 2);
        sum8 += __shfl_xor_sync(0xffffffffu, sum8, 1);
        sum8 += __shfl_xor_sync(0xffffffffu, sum8, 2);
        lrow0 = lrow0 * al0 + sum0;
        lrow8 = lrow8 * al8 + sum8;
#pragma unroll
        for (int ni = 0; ni < 8; ++ni) {
            oacc[ni][0] *= al0; oacc[ni][1] *= al0;
            oacc[ni][2] *= al8; oacc[ni][3] *= al8;
        }

        // --- pack P ---
        uint32_t ph01[8], pl01[8], ph23[8], pl23[8];
#pragma unroll
        for (int ni = 0; ni < 8; ++ni) {
            const float h0 = bf16val(sv[ni][0]), h1 = bf16val(sv[ni][1]);
            ph01[ni] = pk2(h0, h1);
            pl01[ni] = pk2(sv[ni][0] - h0, sv[ni][1] - h1);
            const float h2 = bf16val(sv[ni][2]), h3 = bf16val(sv[ni][3]);
            ph23[ni] = pk2(h2, h3);
            pl23[ni] = pk2(sv[ni][2] - h2, sv[ni][3] - h3);
        }

        // --- O += P V (3x split) ---
#pragma unroll
        for (int j = 0; j < 4; ++j) {
            const int kb = j * 8;
            uint32_t ah[4]  = { ph01[2 * j], ph23[2 * j], ph01[2 * j + 1], ph23[2 * j + 1] };
            uint32_t alr[4] = { pl01[2 * j], pl23[2 * j], pl01[2 * j + 1], pl23[2 * j + 1] };
#pragma unroll
            for (int ni = 0; ni < 8; ++ni) {
                const int c0 = ni * 8 + g;
                uint32_t bh[2] = { VHp[(kb + tg) * 72 + c0], VHp[(kb + tg + 4) * 72 + c0] };
                uint32_t bl[2] = { VLp[(kb + tg) * 72 + c0], VLp[(kb + tg + 4) * 72 + c0] };
                mma16816(oacc[ni], ah, bh);
                mma16816(oacc[ni], ah, bl);
                mma16816(oacc[ni], alr, bh);
            }
        }

        if (t + 1 < NN / 64) {
            AT_STS((t + 1) & 1);
            if (t + 2 < NN / 64) AT_LDG((t + 2) * 64);
        }
        __syncthreads();
    }
#undef AT_LDG
#undef AT_STS

    // --- epilogue: normalize, stage per-warp [64 dk][17], coalesced store ---
    const float inv0 = 1.f / lrow0, inv8 = 1.f / lrow8;
    float* os = (float*)smu + warp * (64 * 17);
#pragma unroll
    for (int ni = 0; ni < 8; ++ni) {
        const int dk0 = ni * 8 + tg * 2;
        os[(dk0 + 0) * 17 + g]     = oacc[ni][0] * inv0;
        os[(dk0 + 1) * 17 + g]     = oacc[ni][1] * inv0;
        os[(dk0 + 0) * 17 + 8 + g] = oacc[ni][2] * inv8;
        os[(dk0 + 1) * 17 + 8 + g] = oacc[ni][3] * inv8;
    }
    __syncwarp();
#pragma unroll
    for (int t = 0; t < 2; ++t) {
        const int dk = lane * 2 + t;
        float* dst = g_x + ((size_t)b * DD + (size_t)dk * HH + h) * NN + n0 + rb;
        const float* src = os + dk * 17;
#pragma unroll
        for (int q4 = 0; q4 < 4; ++q4)
            *(float4*)(dst + q4 * 4) =
                make_float4(src[q4 * 4], src[q4 * 4 + 1], src[q4 * 4 + 2], src[q4 * 4 + 3]);
    }
}

// ---------------------------------------------------------------------------
// Launch
// ---------------------------------------------------------------------------
extern "C" void kernel_launch(void* const* d_in, const int* in_sizes, int n_in,
                              void* d_out, int out_size)
{
    const float* init_query = (const float*)d_in[0];
    const float* key_t      = (const float*)d_in[1];
    const float* value      = (const float*)d_in[2];
    const int*   mask       = (const int*)  d_in[3];
    const float* Wq    = (const float*)d_in[4];
    const float* bq    = (const float*)d_in[5];
    const float* Wk    = (const float*)d_in[6];
    const float* bk    = (const float*)d_in[7];
    const float* Wv    = (const float*)d_in[8];
    const float* bv    = (const float*)d_in[9];
    const float* Wm    = (const float*)d_in[10];
    const float* bm    = (const float*)d_in[11];
    const float* W1    = (const float*)d_in[12];
    const float* b1    = (const float*)d_in[13];
    const float* gamma = (const float*)d_in[14];
    const float* beta  = (const float*)d_in[15];
    const float* rmean = (const float*)d_in[16];
    const float* rvar  = (const float*)d_in[17];
    const float* W2    = (const float*)d_in[18];
    const float* b2    = (const float*)d_in[19];
    float* out = (float*)d_out;

    float *p_x, *p_xm, *p_h;
    cudaGetSymbolAddress((void**)&p_x,  g_x);
    cudaGetSymbolAddress((void**)&p_xm, g_xm);
    cudaGetSymbolAddress((void**)&p_h,  g_h);

    cudaFuncSetAttribute(attn_tc_kernel,
                         cudaFuncAttributeMaxDynamicSharedMemorySize, ATT_SMEM);
    cudaFuncSetAttribute(qkv_kernel,
                         cudaFuncAttributeMaxDynamicSharedMemorySize, GEMM_SMEM);
    cudaFuncSetAttribute(gemm_kernel<0>,
                         cudaFuncAttributeMaxDynamicSharedMemorySize, GEMM_SMEM);
    cudaFuncSetAttribute(gemm_kernel<1>,
                         cudaFuncAttributeMaxDynamicSharedMemorySize, GEMM_SMEM);

    // 0) mask -> bitmask
    maskbits_kernel<<<512, 256>>>(mask);
    // 1) q/k/v projections
    qkv_kernel<<<dim3(16, 4, 6), 256, GEMM_SMEM>>>(init_query, key_t, value,
                                                   Wq, bq, Wk, bk, Wv, bv);
    // 2) flash attention -> g_x
    attn_tc_kernel<<<dim3(NN / 64, HH, BB), 128, ATT_SMEM>>>();
    // 3) merge conv
    gemm_kernel<0><<<dim3(16, 4, BB), 256, GEMM_SMEM>>>(Wm, p_x, nullptr, bm,
                                                        nullptr, nullptr, nullptr, nullptr,
                                                        p_xm, DD, DD);
    // 4) W1 @ [xm ; init_query] + BN + ReLU
    gemm_kernel<1><<<dim3(16, 8, BB), 256, GEMM_SMEM>>>(W1, p_xm, init_query, b1,
                                                        rmean, rvar, gamma, beta,
                                                        p_h, DD2, DD2);
    // 5) out = W2 @ h + b2
    gemm_kernel<0><<<dim3(16, 4, BB), 256, GEMM_SMEM>>>(W2, p_h, nullptr, b2,
                                                        nullptr, nullptr, nullptr, nullptr,
                                                        out, DD, DD2);
}